// round 11
// baseline (speedup 1.0000x reference)
#include <cuda_runtime.h>

// Block_line4feature: 4 fixed depthwise 3x3 convs + weighted affine sum + InstanceNorm2d
// collapses to ONE 3x3 stencil + per-image normalization:
//   conv = x*K,  K = [[-4,-2,-1],[-0.5,15,-0.5],[-1,-2,-4]]/15  (zero padding)
//   out  = (conv - mean_img(conv)) * rsqrt(var_img(conv) + 4e-5)
// Input x: [32,4,512,512] f32 -> 128 independent 512x512 images.
//
// Layout (R6): warp covers a 128-col strip, lane owns 4 contiguous cols ->
// one fully coalesced 512B LDG.128 per warp-row. Block (128 thr, 4 warps)
// covers full 512 width x 32-row strip. 2048 blocks/pass, low regs -> high occ.
// Pass 1: stencil + per-block partial sum/sumsq (deterministic, no atomics)
// Pass 2: fold partials (fixed order) + stencil recompute + normalize + store.

#define IMG_H 512
#define IMG_W 512
#define N_IMG 128
#define PX_PER_IMG (IMG_H * IMG_W)

#define ROWS_PER_BLOCK 32
#define STRIPS_PER_IMG (IMG_H / ROWS_PER_BLOCK)          // 16
#define GRID_BLOCKS (N_IMG * STRIPS_PER_IMG)             // 2048

__device__ float g_psum[GRID_BLOCKS];
__device__ float g_psumsq[GRID_BLOCKS];

struct Row {
    union { float4 q; float f[4]; };
    float l, r;   // col-1 and col+4 neighbor values
};

__device__ __forceinline__ void zero_row(Row& b) {
    b.q = make_float4(0.f, 0.f, 0.f, 0.f);
    b.l = 0.f; b.r = 0.f;
}

// lane owns cols [c0, c0+4); warp covers [128*warp, 128*warp+128).
// Interior neighbors via 2 shuffles; warp-strip edges via predicated scalar
// loads (lines are L1-resident: owned by the adjacent warp of the same block).
__device__ __forceinline__ void load_row(Row& b, const float* __restrict__ rowp,
                                         int c0, int lane) {
    b.q = *reinterpret_cast<const float4*>(rowp + c0);
    float lv = __shfl_up_sync(0xffffffffu, b.f[3], 1);
    float rv = __shfl_down_sync(0xffffffffu, b.f[0], 1);
    if (lane == 0)  lv = (c0 == 0)           ? 0.f : __ldg(rowp + c0 - 1);
    if (lane == 31) rv = (c0 + 4 == IMG_W)   ? 0.f : __ldg(rowp + c0 + 4);
    b.l = lv; b.r = rv;
}

// 9-point stencil for 4 pixels. P=row r-1, C=row r, N=row r+1.
__device__ __forceinline__ void conv_row(const Row& P, const Row& C, const Row& N,
                                         float out[4]) {
    const float cA = -4.0f / 15.0f;   // (r-1,c-1), (r+1,c+1)
    const float cB = -2.0f / 15.0f;   // (r-1,c),   (r+1,c)
    const float cC = -1.0f / 15.0f;   // (r-1,c+1), (r+1,c-1)
    const float cD = -1.0f / 30.0f;   // (r,c-1),   (r,c+1)
#pragma unroll
    for (int k = 0; k < 4; ++k) {
        float pl = (k == 0) ? P.l : P.f[k - 1];
        float pr = (k == 3) ? P.r : P.f[k + 1];
        float cl = (k == 0) ? C.l : C.f[k - 1];
        float cr = (k == 3) ? C.r : C.f[k + 1];
        float nl = (k == 0) ? N.l : N.f[k - 1];
        float nr = (k == 3) ? N.r : N.f[k + 1];
        float v = C.f[k];
        v = fmaf(cA, pl + nr, v);
        v = fmaf(cB, P.f[k] + N.f[k], v);
        v = fmaf(cC, pr + nl, v);
        v = fmaf(cD, cl + cr, v);
        out[k] = v;
    }
}

// ---------------- Pass 1: stencil + per-block stats ----------------

#define STEP1(Pb, Cb, Nb, rr) do {                                              \
    if ((rr) + 1 < IMG_H) load_row(Nb, base + ((rr) + 1) * IMG_W, c0, lane);    \
    else                  zero_row(Nb);                                         \
    float cv[4];                                                                \
    conv_row(Pb, Cb, Nb, cv);                                                   \
    _Pragma("unroll")                                                           \
    for (int k = 0; k < 4; ++k) { s += cv[k]; s2 = fmaf(cv[k], cv[k], s2); }    \
} while (0)

__global__ __launch_bounds__(128, 8) void pass1_kernel(const float* __restrict__ x) {
    const int lane = threadIdx.x & 31;
    const int warp = threadIdx.x >> 5;
    const int img = blockIdx.x / STRIPS_PER_IMG;
    const int r0 = (blockIdx.x % STRIPS_PER_IMG) * ROWS_PER_BLOCK;
    const int c0 = warp * 128 + lane * 4;
    const float* base = x + (size_t)img * PX_PER_IMG;

    Row A, B, C;
    if (r0 == 0) zero_row(A);
    else         load_row(A, base + (r0 - 1) * IMG_W, c0, lane);
    load_row(B, base + r0 * IMG_W, c0, lane);

    float s = 0.f, s2 = 0.f;
#pragma unroll 1
    for (int r = r0; r < r0 + 30; r += 3) {
        STEP1(A, B, C, r);
        STEP1(B, C, A, r + 1);
        STEP1(C, A, B, r + 2);
    }
    // 32 rows = 10*3 + 2; after 10 rotations roles are back to (A=prev, B=cur)
    STEP1(A, B, C, r0 + 30);
    STEP1(B, C, A, r0 + 31);

    // warp reduce (fixed butterfly order -> deterministic)
#pragma unroll
    for (int off = 16; off > 0; off >>= 1) {
        s  += __shfl_xor_sync(0xffffffffu, s,  off);
        s2 += __shfl_xor_sync(0xffffffffu, s2, off);
    }

    __shared__ float sh_s[4], sh_s2[4];
    if (lane == 0) { sh_s[warp] = s; sh_s2[warp] = s2; }
    __syncthreads();
    if (threadIdx.x == 0) {
        float bs = 0.f, bs2 = 0.f;
#pragma unroll
        for (int w = 0; w < 4; ++w) { bs += sh_s[w]; bs2 += sh_s2[w]; }
        g_psum[blockIdx.x] = bs;
        g_psumsq[blockIdx.x] = bs2;
    }
}

// ---------------- Pass 2: fold stats + stencil recompute + normalize ----------------

#define STEP2(Pb, Cb, Nb, rr) do {                                              \
    if ((rr) + 1 < IMG_H) load_row(Nb, base + ((rr) + 1) * IMG_W, c0, lane);    \
    else                  zero_row(Nb);                                         \
    float cv[4];                                                                \
    conv_row(Pb, Cb, Nb, cv);                                                   \
    float4 o;                                                                   \
    o.x = (cv[0] - mean) * rstd;                                                \
    o.y = (cv[1] - mean) * rstd;                                                \
    o.z = (cv[2] - mean) * rstd;                                                \
    o.w = (cv[3] - mean) * rstd;                                                \
    *reinterpret_cast<float4*>(obase + (rr) * IMG_W + c0) = o;                  \
} while (0)

__global__ __launch_bounds__(128, 8) void pass2_kernel(const float* __restrict__ x,
                                                       float* __restrict__ out) {
    const int lane = threadIdx.x & 31;
    const int warp = threadIdx.x >> 5;
    const int img = blockIdx.x / STRIPS_PER_IMG;
    const int r0 = (blockIdx.x % STRIPS_PER_IMG) * ROWS_PER_BLOCK;
    const int c0 = warp * 128 + lane * 4;
    const float* base = x + (size_t)img * PX_PER_IMG;
    float* obase = out + (size_t)img * PX_PER_IMG;

    // Fold the 16 per-strip partials for this image in fixed order (deterministic,
    // identical result in every block of the image). Uniform broadcast L2 loads.
    float s = 0.f, s2 = 0.f;
#pragma unroll
    for (int b = 0; b < STRIPS_PER_IMG; ++b) {
        s  += __ldg(&g_psum[img * STRIPS_PER_IMG + b]);
        s2 += __ldg(&g_psumsq[img * STRIPS_PER_IMG + b]);
    }
    const float inv_n = 1.0f / (float)PX_PER_IMG;
    const float mean = s * inv_n;
    const float var = fmaf(s2, inv_n, -mean * mean);
    const float rstd = rsqrtf(var + 4e-5f);   // 4 * InstanceNorm eps, from affine fold

    Row A, B, C;
    if (r0 == 0) zero_row(A);
    else         load_row(A, base + (r0 - 1) * IMG_W, c0, lane);
    load_row(B, base + r0 * IMG_W, c0, lane);

#pragma unroll 1
    for (int r = r0; r < r0 + 30; r += 3) {
        STEP2(A, B, C, r);
        STEP2(B, C, A, r + 1);
        STEP2(C, A, B, r + 2);
    }
    STEP2(A, B, C, r0 + 30);
    STEP2(B, C, A, r0 + 31);
}

extern "C" void kernel_launch(void* const* d_in, const int* in_sizes, int n_in,
                              void* d_out, int out_size) {
    const float* x = (const float*)d_in[0];
    float* out = (float*)d_out;
    (void)in_sizes; (void)n_in; (void)out_size;

    pass1_kernel<<<GRID_BLOCKS, 128>>>(x);
    pass2_kernel<<<GRID_BLOCKS, 128>>>(x, out);
}

// round 13
// speedup vs baseline: 1.2649x; 1.2649x over previous
#include <cuda_runtime.h>

// Block_line4feature: 4 fixed depthwise 3x3 convs + weighted affine sum + InstanceNorm2d
// collapses to ONE 3x3 stencil + per-image normalization:
//   conv = x*K,  K = [[-4,-2,-1],[-0.5,15,-0.5],[-1,-2,-4]]/15  (zero padding)
//   out  = (conv - mean_img(conv)) * rsqrt(var_img(conv) + 4e-5)
// Input x: [32,4,512,512] f32 -> 128 independent 512x512 images.
//
// Coalesced layout (lane owns 4 contiguous cols, warp = 128-col strip,
// block = 512 cols x 32 rows) + 3-row software pipeline: each iteration issues
// 3 independent row loads back-to-back (MLP=3+) before any shuffle/conv consumes
// them. Main loop is branch-free (rows r+1..r+3 <= 510 always in-bounds).

#define IMG_H 512
#define IMG_W 512
#define N_IMG 128
#define PX_PER_IMG (IMG_H * IMG_W)

#define ROWS_PER_BLOCK 32
#define STRIPS_PER_IMG (IMG_H / ROWS_PER_BLOCK)          // 16
#define GRID_BLOCKS (N_IMG * STRIPS_PER_IMG)             // 2048

__device__ float g_psum[GRID_BLOCKS];
__device__ float g_psumsq[GRID_BLOCKS];

struct Row {
    union { float4 q; float f[4]; };
    float l, r;   // col-1 and col+4 neighbor values
};

__device__ __forceinline__ void zero_row(Row& b) {
    b.q = make_float4(0.f, 0.f, 0.f, 0.f);
    b.l = 0.f; b.r = 0.f;
}

// Issue the loads only (vector + predicated edge scalars). No shuffles here, so
// consecutive load_raw calls produce back-to-back independent LDGs (high MLP).
__device__ __forceinline__ void load_raw(Row& b, const float* __restrict__ rowp,
                                         int c0, int lane) {
    b.q = *reinterpret_cast<const float4*>(rowp + c0);
    b.l = 0.f; b.r = 0.f;
    if (lane == 0  && c0 != 0)            b.l = __ldg(rowp + c0 - 1);
    if (lane == 31 && c0 + 4 != IMG_W)    b.r = __ldg(rowp + c0 + 4);
}

// Cross-lane neighbor exchange (after the batched loads have been issued).
__device__ __forceinline__ void finish_row(Row& b, int lane) {
    float lv = __shfl_up_sync(0xffffffffu, b.f[3], 1);
    float rv = __shfl_down_sync(0xffffffffu, b.f[0], 1);
    if (lane != 0)  b.l = lv;   // lane 0 keeps its __ldg/zero value
    if (lane != 31) b.r = rv;   // lane 31 keeps its __ldg/zero value
}

// 9-point stencil for 4 pixels. P=row r-1, C=row r, N=row r+1.
__device__ __forceinline__ void conv_row(const Row& P, const Row& C, const Row& N,
                                         float out[4]) {
    const float cA = -4.0f / 15.0f;   // (r-1,c-1), (r+1,c+1)
    const float cB = -2.0f / 15.0f;   // (r-1,c),   (r+1,c)
    const float cC = -1.0f / 15.0f;   // (r-1,c+1), (r+1,c-1)
    const float cD = -1.0f / 30.0f;   // (r,c-1),   (r,c+1)
#pragma unroll
    for (int k = 0; k < 4; ++k) {
        float pl = (k == 0) ? P.l : P.f[k - 1];
        float pr = (k == 3) ? P.r : P.f[k + 1];
        float cl = (k == 0) ? C.l : C.f[k - 1];
        float cr = (k == 3) ? C.r : C.f[k + 1];
        float nl = (k == 0) ? N.l : N.f[k - 1];
        float nr = (k == 3) ? N.r : N.f[k + 1];
        float v = C.f[k];
        v = fmaf(cA, pl + nr, v);
        v = fmaf(cB, P.f[k] + N.f[k], v);
        v = fmaf(cC, pr + nl, v);
        v = fmaf(cD, cl + cr, v);
        out[k] = v;
    }
}

// ---------------- Pass 1: stencil + per-block stats ----------------

#define ACC1(Pb, Cb, Nb) do {                                                   \
    float cv[4];                                                                \
    conv_row(Pb, Cb, Nb, cv);                                                   \
    _Pragma("unroll")                                                           \
    for (int k = 0; k < 4; ++k) { s += cv[k]; s2 = fmaf(cv[k], cv[k], s2); }    \
} while (0)

__global__ __launch_bounds__(128, 6) void pass1_kernel(const float* __restrict__ x) {
    const int lane = threadIdx.x & 31;
    const int warp = threadIdx.x >> 5;
    const int img = blockIdx.x / STRIPS_PER_IMG;
    const int r0 = (blockIdx.x % STRIPS_PER_IMG) * ROWS_PER_BLOCK;
    const int c0 = warp * 128 + lane * 4;
    const float* base = x + (size_t)img * PX_PER_IMG;

    Row A, B;
    if (r0 == 0) zero_row(A);
    else { load_raw(A, base + (r0 - 1) * IMG_W, c0, lane); finish_row(A, lane); }
    load_raw(B, base + r0 * IMG_W, c0, lane); finish_row(B, lane);

    float s = 0.f, s2 = 0.f;
#pragma unroll 1
    for (int r = r0; r < r0 + 30; r += 3) {
        // rows r+1..r+3 <= r0+30 <= 510: always in-bounds, no branches.
        Row N1, N2, N3;
        load_raw(N1, base + (r + 1) * IMG_W, c0, lane);
        load_raw(N2, base + (r + 2) * IMG_W, c0, lane);
        load_raw(N3, base + (r + 3) * IMG_W, c0, lane);
        finish_row(N1, lane); finish_row(N2, lane); finish_row(N3, lane);
        ACC1(A, B, N1);     // row r
        ACC1(B, N1, N2);    // row r+1
        ACC1(N1, N2, N3);   // row r+2
        A = N2; B = N3;
    }
    { // tail rows r0+30, r0+31 (halo row r0+32 may cross into next strip / image edge)
        Row N1, N2;
        load_raw(N1, base + (r0 + 31) * IMG_W, c0, lane);
        if (r0 + 32 < IMG_H) load_raw(N2, base + (r0 + 32) * IMG_W, c0, lane);
        else                 zero_row(N2);
        finish_row(N1, lane); finish_row(N2, lane);
        ACC1(A, B, N1);
        ACC1(B, N1, N2);
    }

    // warp reduce (fixed butterfly order -> deterministic)
#pragma unroll
    for (int off = 16; off > 0; off >>= 1) {
        s  += __shfl_xor_sync(0xffffffffu, s,  off);
        s2 += __shfl_xor_sync(0xffffffffu, s2, off);
    }
    __shared__ float sh_s[4], sh_s2[4];
    if (lane == 0) { sh_s[warp] = s; sh_s2[warp] = s2; }
    __syncthreads();
    if (threadIdx.x == 0) {
        float bs = 0.f, bs2 = 0.f;
#pragma unroll
        for (int w = 0; w < 4; ++w) { bs += sh_s[w]; bs2 += sh_s2[w]; }
        g_psum[blockIdx.x] = bs;
        g_psumsq[blockIdx.x] = bs2;
    }
}

// ---------------- Pass 2: fold stats + stencil recompute + normalize ----------------

#define EMIT2(Pb, Cb, Nb, rr) do {                                              \
    float cv[4];                                                                \
    conv_row(Pb, Cb, Nb, cv);                                                   \
    float4 o;                                                                   \
    o.x = (cv[0] - mean) * rstd;                                                \
    o.y = (cv[1] - mean) * rstd;                                                \
    o.z = (cv[2] - mean) * rstd;                                                \
    o.w = (cv[3] - mean) * rstd;                                                \
    *reinterpret_cast<float4*>(obase + (rr) * IMG_W + c0) = o;                  \
} while (0)

__global__ __launch_bounds__(128, 6) void pass2_kernel(const float* __restrict__ x,
                                                       float* __restrict__ out) {
    const int lane = threadIdx.x & 31;
    const int warp = threadIdx.x >> 5;
    const int img = blockIdx.x / STRIPS_PER_IMG;
    const int r0 = (blockIdx.x % STRIPS_PER_IMG) * ROWS_PER_BLOCK;
    const int c0 = warp * 128 + lane * 4;
    const float* base = x + (size_t)img * PX_PER_IMG;
    float* obase = out + (size_t)img * PX_PER_IMG;

    // Fold the 16 per-strip partials for this image in fixed order (deterministic,
    // identical result in every block of the image). Uniform broadcast L2 loads.
    float s = 0.f, s2 = 0.f;
#pragma unroll
    for (int b = 0; b < STRIPS_PER_IMG; ++b) {
        s  += __ldg(&g_psum[img * STRIPS_PER_IMG + b]);
        s2 += __ldg(&g_psumsq[img * STRIPS_PER_IMG + b]);
    }
    const float inv_n = 1.0f / (float)PX_PER_IMG;
    const float mean = s * inv_n;
    const float var = fmaf(s2, inv_n, -mean * mean);
    const float rstd = rsqrtf(var + 4e-5f);   // 4 * InstanceNorm eps, from affine fold

    Row A, B;
    if (r0 == 0) zero_row(A);
    else { load_raw(A, base + (r0 - 1) * IMG_W, c0, lane); finish_row(A, lane); }
    load_raw(B, base + r0 * IMG_W, c0, lane); finish_row(B, lane);

#pragma unroll 1
    for (int r = r0; r < r0 + 30; r += 3) {
        Row N1, N2, N3;
        load_raw(N1, base + (r + 1) * IMG_W, c0, lane);
        load_raw(N2, base + (r + 2) * IMG_W, c0, lane);
        load_raw(N3, base + (r + 3) * IMG_W, c0, lane);
        finish_row(N1, lane); finish_row(N2, lane); finish_row(N3, lane);
        EMIT2(A, B, N1, r);
        EMIT2(B, N1, N2, r + 1);
        EMIT2(N1, N2, N3, r + 2);
        A = N2; B = N3;
    }
    {
        Row N1, N2;
        load_raw(N1, base + (r0 + 31) * IMG_W, c0, lane);
        if (r0 + 32 < IMG_H) load_raw(N2, base + (r0 + 32) * IMG_W, c0, lane);
        else                 zero_row(N2);
        finish_row(N1, lane); finish_row(N2, lane);
        EMIT2(A, B, N1, r0 + 30);
        EMIT2(B, N1, N2, r0 + 31);
    }
}

extern "C" void kernel_launch(void* const* d_in, const int* in_sizes, int n_in,
                              void* d_out, int out_size) {
    const float* x = (const float*)d_in[0];
    float* out = (float*)d_out;
    (void)in_sizes; (void)n_in; (void)out_size;

    pass1_kernel<<<GRID_BLOCKS, 128>>>(x);
    pass2_kernel<<<GRID_BLOCKS, 128>>>(x, out);
}

// round 17
// speedup vs baseline: 1.5019x; 1.1874x over previous
#include <cuda_runtime.h>

// Block_line4feature: 4 fixed depthwise 3x3 convs + weighted affine sum + InstanceNorm2d
// collapses to ONE 3x3 stencil + per-image normalization:
//   conv = x*K,  K = [[-4,-2,-1],[-0.5,15,-0.5],[-1,-2,-4]]/15  (zero padding)
//   out  = (conv - mean_img(conv)) * rsqrt(var_img(conv) + 4e-5)
// Input x: [32,4,512,512] f32 -> 128 independent 512x512 images.
//
// FUSED single kernel: one 1024-thread block per image (128 blocks, 1 wave).
//   Phase 1 (forward): stencil + block-wide sum/sumsq -> mean, rstd (deterministic).
//   Phase 2 (BACKWARD): stencil recompute + normalize + store. Backward order
//   re-reads the image's 1MB most-recently-touched-first, so reads hit L2
//   (128 x 1MB ~ L2 capacity). DRAM traffic: 256MB total vs 384MB two-pass.
// Warp layout: lane owns 4 contiguous cols (coalesced 512B LDG.128 per row);
// warp w covers strip (w&3)*128 cols x 64-row group (w>>2). 3-row load batches
// keep MLP >= 3 per warp.

#define IMG_H 512
#define IMG_W 512
#define N_IMG 128
#define PX_PER_IMG (IMG_H * IMG_W)

#define THREADS 1024
#define N_WARPS 32
#define ROWS_PER_WARP 64          // 8 row-groups * 64 = 512

struct Row {
    union { float4 q; float f[4]; };
    float l, r;   // col-1 and col+4 neighbor values
};

__device__ __forceinline__ void zero_row(Row& b) {
    b.q = make_float4(0.f, 0.f, 0.f, 0.f);
    b.l = 0.f; b.r = 0.f;
}

// Issue loads only (vector + predicated edge scalars); no shuffles, so
// consecutive load_raw calls produce back-to-back independent LDGs (high MLP).
__device__ __forceinline__ void load_raw(Row& b, const float* __restrict__ rowp,
                                         int c0, int lane) {
    b.q = *reinterpret_cast<const float4*>(rowp + c0);
    b.l = 0.f; b.r = 0.f;
    if (lane == 0  && c0 != 0)            b.l = __ldg(rowp + c0 - 1);
    if (lane == 31 && c0 + 4 != IMG_W)    b.r = __ldg(rowp + c0 + 4);
}

// Cross-lane neighbor exchange (after batched loads issued).
__device__ __forceinline__ void finish_row(Row& b, int lane) {
    float lv = __shfl_up_sync(0xffffffffu, b.f[3], 1);
    float rv = __shfl_down_sync(0xffffffffu, b.f[0], 1);
    if (lane != 0)  b.l = lv;
    if (lane != 31) b.r = rv;
}

// 9-point stencil for 4 pixels. P=row r-1, C=row r, N=row r+1.
__device__ __forceinline__ void conv_row(const Row& P, const Row& C, const Row& N,
                                         float out[4]) {
    const float cA = -4.0f / 15.0f;   // (r-1,c-1), (r+1,c+1)
    const float cB = -2.0f / 15.0f;   // (r-1,c),   (r+1,c)
    const float cC = -1.0f / 15.0f;   // (r-1,c+1), (r+1,c-1)
    const float cD = -1.0f / 30.0f;   // (r,c-1),   (r,c+1)
#pragma unroll
    for (int k = 0; k < 4; ++k) {
        float pl = (k == 0) ? P.l : P.f[k - 1];
        float pr = (k == 3) ? P.r : P.f[k + 1];
        float cl = (k == 0) ? C.l : C.f[k - 1];
        float cr = (k == 3) ? C.r : C.f[k + 1];
        float nl = (k == 0) ? N.l : N.f[k - 1];
        float nr = (k == 3) ? N.r : N.f[k + 1];
        float v = C.f[k];
        v = fmaf(cA, pl + nr, v);
        v = fmaf(cB, P.f[k] + N.f[k], v);
        v = fmaf(cC, pr + nl, v);
        v = fmaf(cD, cl + cr, v);
        out[k] = v;
    }
}

#define ACC(Pb, Cb, Nb) do {                                                    \
    float cv[4];                                                                \
    conv_row(Pb, Cb, Nb, cv);                                                   \
    _Pragma("unroll")                                                           \
    for (int k = 0; k < 4; ++k) { s += cv[k]; s2 = fmaf(cv[k], cv[k], s2); }    \
} while (0)

#define EMIT(Pb, Cb, Nb, rr) do {                                               \
    float cv[4];                                                                \
    conv_row(Pb, Cb, Nb, cv);                                                   \
    float4 o;                                                                   \
    o.x = (cv[0] - mean) * rstd;                                                \
    o.y = (cv[1] - mean) * rstd;                                                \
    o.z = (cv[2] - mean) * rstd;                                                \
    o.w = (cv[3] - mean) * rstd;                                                \
    *reinterpret_cast<float4*>(obase + (rr) * IMG_W + c0) = o;                  \
} while (0)

__global__ __launch_bounds__(THREADS) void fused_kernel(const float* __restrict__ x,
                                                        float* __restrict__ out) {
    const int lane = threadIdx.x & 31;
    const int warp = threadIdx.x >> 5;
    const int img = blockIdx.x;
    const int c0 = (warp & 3) * 128 + lane * 4;        // 4 strips of 128 cols
    const int r0 = (warp >> 2) * ROWS_PER_WARP;        // 8 groups of 64 rows
    const float* base = x + (size_t)img * PX_PER_IMG;
    float* obase = out + (size_t)img * PX_PER_IMG;

    __shared__ float sh_s[N_WARPS], sh_s2[N_WARPS];
    __shared__ float sh_mean, sh_rstd;

    // ---------------- Phase 1: forward stencil + stats ----------------
    float s = 0.f, s2 = 0.f;
    {
        Row A, B;
        if (r0 == 0) zero_row(A);
        else { load_raw(A, base + (r0 - 1) * IMG_W, c0, lane); finish_row(A, lane); }
        load_raw(B, base + r0 * IMG_W, c0, lane); finish_row(B, lane);

#pragma unroll 1
        for (int r = r0; r < r0 + 63; r += 3) {
            // loads r+1..r+3 <= r0+63 <= 511: always in-bounds
            Row N1, N2, N3;
            load_raw(N1, base + (r + 1) * IMG_W, c0, lane);
            load_raw(N2, base + (r + 2) * IMG_W, c0, lane);
            load_raw(N3, base + (r + 3) * IMG_W, c0, lane);
            finish_row(N1, lane); finish_row(N2, lane); finish_row(N3, lane);
            ACC(A, B, N1);      // row r
            ACC(B, N1, N2);     // row r+1
            ACC(N1, N2, N3);    // row r+2
            A = N2; B = N3;
        }
        { // tail row r0+63 (halo row r0+64 may be out of image)
            Row N;
            if (r0 + 64 < IMG_H) { load_raw(N, base + (r0 + 64) * IMG_W, c0, lane); finish_row(N, lane); }
            else                 zero_row(N);
            ACC(A, B, N);
        }
    }

    // Deterministic block reduction: warp butterfly -> smem -> warp0 butterfly.
#pragma unroll
    for (int off = 16; off > 0; off >>= 1) {
        s  += __shfl_xor_sync(0xffffffffu, s,  off);
        s2 += __shfl_xor_sync(0xffffffffu, s2, off);
    }
    if (lane == 0) { sh_s[warp] = s; sh_s2[warp] = s2; }
    __syncthreads();
    if (warp == 0) {
        float a = sh_s[lane], a2 = sh_s2[lane];
#pragma unroll
        for (int off = 16; off > 0; off >>= 1) {
            a  += __shfl_xor_sync(0xffffffffu, a,  off);
            a2 += __shfl_xor_sync(0xffffffffu, a2, off);
        }
        if (lane == 0) {
            const float inv_n = 1.0f / (float)PX_PER_IMG;
            float mean = a * inv_n;
            float var = fmaf(a2, inv_n, -mean * mean);
            sh_mean = mean;
            sh_rstd = rsqrtf(var + 4e-5f);   // 4 * InstanceNorm eps, from affine fold
        }
    }
    __syncthreads();
    const float mean = sh_mean;
    const float rstd = sh_rstd;

    // ---------------- Phase 2: BACKWARD stencil + normalize + store ----------------
    // Bottom-up order re-reads most-recently-touched lines first (L2 LIFO reuse).
    {
        const int rt = r0 + ROWS_PER_WARP - 1;   // top of this warp's group (last row)
        Row A, B;                                 // A = row r+1, B = row r
        if (rt + 1 < IMG_H) { load_raw(A, base + (rt + 1) * IMG_W, c0, lane); finish_row(A, lane); }
        else                zero_row(A);
        load_raw(B, base + rt * IMG_W, c0, lane); finish_row(B, lane);

#pragma unroll 1
        for (int r = rt; r > r0; r -= 3) {
            // loads r-1..r-3 >= r0 (r >= r0+3): always in-bounds
            Row N1, N2, N3;
            load_raw(N1, base + (r - 1) * IMG_W, c0, lane);
            load_raw(N2, base + (r - 2) * IMG_W, c0, lane);
            load_raw(N3, base + (r - 3) * IMG_W, c0, lane);
            finish_row(N1, lane); finish_row(N2, lane); finish_row(N3, lane);
            EMIT(N1, B, A, r);          // row r   : P=r-1, C=r,   N=r+1
            EMIT(N2, N1, B, r - 1);     // row r-1
            EMIT(N3, N2, N1, r - 2);    // row r-2
            A = N2; B = N3;             // B = row r-3, A = row r-2
        }
        { // tail row r0 (halo row r0-1 may be out of image)
            Row P;
            if (r0 > 0) { load_raw(P, base + (r0 - 1) * IMG_W, c0, lane); finish_row(P, lane); }
            else        zero_row(P);
            EMIT(P, B, A, r0);
        }
    }
}

extern "C" void kernel_launch(void* const* d_in, const int* in_sizes, int n_in,
                              void* d_out, int out_size) {
    const float* x = (const float*)d_in[0];
    float* out = (float*)d_out;
    (void)in_sizes; (void)n_in; (void)out_size;

    fused_kernel<<<N_IMG, THREADS>>>(x, out);
}